// round 13
// baseline (speedup 1.0000x reference)
#include <cuda_runtime.h>

#define BSZ 4096
#define TSZ 4096
#define NTOT ((long)BSZ * TSZ)

// per-chain loss partials
__device__ double g_loss_partial[BSZ];

__device__ __forceinline__ float tanhx(float x) {
    float y; asm("tanh.approx.f32 %0, %1;" : "=f"(y) : "f"(x)); return y;
}

// 4 lanes per chain (roles 0..2 own h0..h2, role 3 mirrors role 2).
// 8 chains per warp, 4 warps per block, 128 blocks -> 4096 chains, 1 warp/SMSP.
// Fully fused: writes x_pad + masked output directly, accumulates loss.
__global__ void __launch_bounds__(128, 1) gru_kernel(
    const float* __restrict__ x, const int* __restrict__ lens,
    const float* __restrict__ eWih, const float* __restrict__ eWhh,
    const float* __restrict__ ebih, const float* __restrict__ ebhh,
    const float* __restrict__ dWih, const float* __restrict__ dWhh,
    const float* __restrict__ dbih, const float* __restrict__ dbhh,
    const float* __restrict__ linW, const float* __restrict__ linb,
    float* __restrict__ out_xpad, float* __restrict__ out_output)
{
    const unsigned FULL = 0xFFFFFFFFu;
    const int lane  = threadIdx.x & 31;
    const int warp  = threadIdx.x >> 5;
    const int group = lane >> 2;
    const int role  = lane & 3;
    const int k     = (role == 3) ? 2 : role;
    int kA = k + 1; if (kA == 3) kA = 0;
    int kB = k + 2; if (kB >= 3) kB -= 3;
    const int base = lane & ~3;
    const int srcA = base + kA;
    const int srcB = base + kB;

    const int chain = (blockIdx.x * 4 + warp) * 8 + group;
    const int len   = lens[chain];
    const int len_m1 = len - 1;
    const float* __restrict__ xrow  = x + (long)chain * TSZ;
    float* __restrict__ xprow = out_xpad   + (long)chain * TSZ;
    float* __restrict__ orow  = out_output + (long)chain * TSZ;

    float h = 0.f, hA = 0.f, hB = 0.f;
    float c = 0.f;                         // captured own component at t == len-1

    // ================= encoder =================
    {
        const float ewr_x = 0.5f * eWih[k];
        const float ewr_b = 0.5f * (ebih[k] + ebhh[k]);
        const float ewr_o = 0.5f * eWhh[k * 3 + k];
        const float ewr_A = 0.5f * eWhh[k * 3 + kA];
        const float ewr_B = 0.5f * eWhh[k * 3 + kB];
        const int zr = 3 + k;
        const float ewz_x = 0.5f * eWih[zr];
        const float ewz_b = 0.5f * (ebih[zr] + ebhh[zr]);
        const float ewz_o = 0.5f * eWhh[zr * 3 + k];
        const float ewz_A = 0.5f * eWhh[zr * 3 + kA];
        const float ewz_B = 0.5f * eWhh[zr * 3 + kB];
        const int nr = 6 + k;
        const float ewn_x  = eWih[nr];
        const float ewn_bi = ebih[nr];
        const float ewn_bh = ebhh[nr];
        const float ewn_o  = eWhh[nr * 3 + k];
        const float ewn_A  = eWhh[nr * 3 + kA];
        const float ewn_B  = eWhh[nr * 3 + kB];

        auto enc_step = [&](float xv, int t) {
            float gr = fmaf(xv, ewr_x, ewr_b);
            float gz = fmaf(xv, ewz_x, ewz_b);
            float gn = fmaf(xv, ewn_x, ewn_bi);
            float ar = fmaf(hB, ewr_B, fmaf(hA, ewr_A, fmaf(h, ewr_o, gr)));
            float az = fmaf(hB, ewz_B, fmaf(hA, ewz_A, fmaf(h, ewz_o, gz)));
            float hn = fmaf(hB, ewn_B, fmaf(hA, ewn_A, fmaf(h, ewn_o, ewn_bh)));
            float tr = tanhx(ar);
            float tz = tanhx(az);
            float p = 0.5f * hn;
            float q = fmaf(0.5f, hn, gn);
            float n = tanhx(fmaf(tr, p, q));
            float m = fmaf(tz, -0.5f, 0.5f);
            float u = fmaf(-m, h, h);
            float nh = fmaf(n, m, u);
            bool act = t < len;
            h = act ? nh : h;
            if (t == len_m1) c = h;
            hA = __shfl_sync(FULL, h, srcA);
            hB = __shfl_sync(FULL, h, srcB);
        };

        const int wmax  = __reduce_max_sync(FULL, len);
        const int wmax4 = (wmax + 3) & ~3;
        for (int t = 0; t < wmax4; t += 4) {
            const float4 xq = *(const float4*)(xrow + t);
            enc_step(xq.x, t + 0);
            enc_step(xq.y, t + 1);
            enc_step(xq.z, t + 2);
            enc_step(xq.w, t + 3);
            // x_pad: lane stores its role's element (epilogue, off-chain)
            float xsel = (role == 0) ? xq.x : (role == 1) ? xq.y : (role == 2) ? xq.z : xq.w;
            int tt = t + role;
            xprow[tt] = (tt < len) ? xsel : 0.f;
        }
        // zero the x_pad tail beyond this warp's max length
        for (int t = wmax4; t < TSZ; t += 4)
            xprow[t + role] = 0.f;
    }

    // features = sigmoid(captured own component), then exchange
    h  = fmaf(tanhx(0.5f * c), 0.5f, 0.5f);
    hA = __shfl_sync(FULL, h, srcA);
    hB = __shfl_sync(FULL, h, srcB);

    // ================= decoder (linear layer folded into gates) =================
    {
        const float lw_o = linW[k], lw_A = linW[kA], lw_B = linW[kB], lb = linb[0];

        const float wik = dWih[k];
        const float dr_o = 0.5f * fmaf(wik, lw_o, dWhh[k * 3 + k]);
        const float dr_A = 0.5f * fmaf(wik, lw_A, dWhh[k * 3 + kA]);
        const float dr_B = 0.5f * fmaf(wik, lw_B, dWhh[k * 3 + kB]);
        const float dr_b = 0.5f * (dbih[k] + dbhh[k] + wik * lb);
        const float wiz = dWih[3 + k];
        const float dz_o = 0.5f * fmaf(wiz, lw_o, dWhh[(3 + k) * 3 + k]);
        const float dz_A = 0.5f * fmaf(wiz, lw_A, dWhh[(3 + k) * 3 + kA]);
        const float dz_B = 0.5f * fmaf(wiz, lw_B, dWhh[(3 + k) * 3 + kB]);
        const float dz_b = 0.5f * (dbih[3 + k] + dbhh[3 + k] + wiz * lb);
        const float win = dWih[6 + k];
        const float di_o = win * lw_o;
        const float di_A = win * lw_A;
        const float di_B = win * lw_B;
        const float di_b = fmaf(win, lb, dbih[6 + k]);
        const float dn_o = dWhh[(6 + k) * 3 + k];
        const float dn_A = dWhh[(6 + k) * 3 + kA];
        const float dn_B = dWhh[(6 + k) * 3 + kB];
        const float dn_b = dbhh[6 + k];

        auto dec_step = [&]() -> float {
            float ar = fmaf(hB, dr_B, fmaf(hA, dr_A, fmaf(h, dr_o, dr_b)));
            float az = fmaf(hB, dz_B, fmaf(hA, dz_A, fmaf(h, dz_o, dz_b)));
            float hn = fmaf(hB, dn_B, fmaf(hA, dn_A, fmaf(h, dn_o, dn_b)));
            float gi = fmaf(hB, di_B, fmaf(hA, di_A, fmaf(h, di_o, di_b)));
            float tr = tanhx(ar);
            float tz = tanhx(az);
            float p = 0.5f * hn;
            float q = fmaf(0.5f, hn, gi);
            float n = tanhx(fmaf(tr, p, q));
            float m = fmaf(tz, -0.5f, 0.5f);
            float u = fmaf(-m, h, h);
            h = fmaf(n, m, u);
            hA = __shfl_sync(FULL, h, srcA);
            hB = __shfl_sync(FULL, h, srcB);
            return fmaf(hB, lw_B, fmaf(hA, lw_A, fmaf(h, lw_o, lb)));
        };

        float acc0 = 0.f, acc1 = 0.f;
        // prefetch this lane's x element for quad 0
        float xv_cur = xrow[role];

        // ---- step 0 (inp = 0): unfolded ----
        float o_first;
        {
            float ar = 0.5f * (dbih[k] + dbhh[k]
                     + fmaf(hB, dWhh[k * 3 + kB], fmaf(hA, dWhh[k * 3 + kA], h * dWhh[k * 3 + k])));
            float az = 0.5f * (dbih[3 + k] + dbhh[3 + k]
                     + fmaf(hB, dWhh[(3 + k) * 3 + kB], fmaf(hA, dWhh[(3 + k) * 3 + kA], h * dWhh[(3 + k) * 3 + k])));
            float hn = dbhh[6 + k]
                     + fmaf(hB, dWhh[(6 + k) * 3 + kB], fmaf(hA, dWhh[(6 + k) * 3 + kA], h * dWhh[(6 + k) * 3 + k]));
            float r = fmaf(tanhx(ar), 0.5f, 0.5f);
            float n = tanhx(fmaf(r, hn, dbih[6 + k]));
            float m = fmaf(tanhx(az), -0.5f, 0.5f);
            float u = fmaf(-m, h, h);
            h = fmaf(n, m, u);
            hA = __shfl_sync(FULL, h, srcA);
            hB = __shfl_sync(FULL, h, srcB);
            o_first = fmaf(hB, lw_B, fmaf(hA, lw_A, fmaf(h, lw_o, lb)));
        }
        // ---- steps 1..3, epilogue for quad 0 ----
        {
            float o1 = dec_step();
            float o2 = dec_step();
            float o3 = dec_step();
            float xv_next = xrow[4 + role];                 // prefetch quad 1
            float osel = (role == 0) ? o_first : (role == 1) ? o1 : (role == 2) ? o2 : o3;
            bool valid = role < len;                        // tt = 0 + role
            float om = valid ? osel : 0.f;
            orow[role] = om;
            float xm = valid ? xv_cur : 0.f;
            float d = xm - om;
            acc0 = fmaf(d, d, acc0);
            xv_cur = xv_next;
        }
        // ---- quads at t = 4..4092 ----
        for (int t = 4; t < TSZ; t += 4) {
            float o0 = dec_step();
            float o1 = dec_step();
            float o2 = dec_step();
            float o3 = dec_step();
            int tn = (t + 4 < TSZ) ? (t + 4) : (TSZ - 4);   // clamped prefetch
            float xv_next = xrow[tn + role];
            float osel = (role == 0) ? o0 : (role == 1) ? o1 : (role == 2) ? o2 : o3;
            int tt = t + role;
            bool valid = tt < len;
            float om = valid ? osel : 0.f;
            orow[tt] = om;
            float xm = valid ? xv_cur : 0.f;
            float d = xm - om;
            if (t & 4) acc1 = fmaf(d, d, acc1); else acc0 = fmaf(d, d, acc0);
            xv_cur = xv_next;
        }

        // reduce loss partials across the 4 lanes of the quad (deterministic order)
        float accw = acc0 + acc1;
        double accd = (double)accw;
        accd += __shfl_xor_sync(FULL, accd, 1);
        accd += __shfl_xor_sync(FULL, accd, 2);
        if (role == 3) g_loss_partial[chain] = accd;
    }
}

// Deterministic fixed-order reduction of the 4096 partials -> scalar loss
__global__ void loss_kernel(float* __restrict__ out_loss)
{
    __shared__ double s[1024];
    int tid = threadIdx.x;
    double a = 0.0;
    for (int i = tid; i < BSZ; i += 1024) a += g_loss_partial[i];
    s[tid] = a;
    __syncthreads();
    for (int off = 512; off > 0; off >>= 1) {
        if (tid < off) s[tid] += s[tid + off];
        __syncthreads();
    }
    if (tid == 0) out_loss[0] = (float)(s[0] / ((double)BSZ * (double)TSZ));
}

extern "C" void kernel_launch(void* const* d_in, const int* in_sizes, int n_in,
                              void* d_out, int out_size)
{
    const float* x    = (const float*)d_in[0];
    const int*   lens = (const int*)  d_in[1];
    const float* eWih = (const float*)d_in[2];
    const float* eWhh = (const float*)d_in[3];
    const float* ebih = (const float*)d_in[4];
    const float* ebhh = (const float*)d_in[5];
    const float* dWih = (const float*)d_in[6];
    const float* dWhh = (const float*)d_in[7];
    const float* dbih = (const float*)d_in[8];
    const float* dbhh = (const float*)d_in[9];
    const float* linW = (const float*)d_in[10];
    const float* linb = (const float*)d_in[11];

    float* out    = (float*)d_out;
    float* loss   = out;                       // [1]
    float* xpad   = out + 1;                   // [B*T]
    float* output = out + 1 + NTOT;            // [B*T]

    gru_kernel<<<128, 128>>>(x, lens, eWih, eWhh, ebih, ebhh,
                             dWih, dWhh, dbih, dbhh, linW, linb,
                             xpad, output);
    loss_kernel<<<1, 1024>>>(loss);
}